// round 8
// baseline (speedup 1.0000x reference)
#include <cuda_runtime.h>
#include <cuda_bf16.h>
#include <cstddef>

#define TPB      1024
#define NFFT     4096
#define CST      4356                 // per-column smem stride (float2)
#define PHYS(i)  ((i) + ((i) >> 4))   // data padding: every 16 elements
#define PHYT(i)  ((i) + ((i) >> 4) + ((i) >> 6))  // twiddle-table padding
#define TWN      256
#define TWSZ     288                  // > PHYT(255) = 273
#define PERM16(m) ((((m) & 3) << 2) | ((m) >> 2))

// Scratch: filter as 2x2 complex linear map per (k, 4096-k) pair.
// slot 2q   = (P.x, P.y, Q.x, Q.y)
// slot 2q+1 = (R.x, R.y, S.x, S.y)
// q==0 special: slot 0 = (H0.re, HN.re, conjH2048.x, conjH2048.y)
__device__ float4 g_Hpack[512 * 4096];

__device__ __forceinline__ float2 cmul(float2 a, float2 b) {
    return make_float2(fmaf(a.x, b.x, -a.y * b.y), fmaf(a.x, b.y, a.y * b.x));
}
// a * conj(b)
__device__ __forceinline__ float2 cmulc(float2 a, float2 b) {
    return make_float2(fmaf(a.x, b.x, a.y * b.y), fmaf(a.y, b.x, -a.x * b.y));
}

__device__ __forceinline__ void dft4(float2 &a, float2 &b, float2 &c, float2 &d) {
    float2 t0 = make_float2(a.x + c.x, a.y + c.y);
    float2 t1 = make_float2(a.x - c.x, a.y - c.y);
    float2 t2 = make_float2(b.x + d.x, b.y + d.y);
    float2 t3 = make_float2(b.x - d.x, b.y - d.y);
    a = make_float2(t0.x + t2.x, t0.y + t2.y);
    c = make_float2(t0.x - t2.x, t0.y - t2.y);
    b = make_float2(t1.x + t3.y, t1.y - t3.x);   // t1 - i*t3
    d = make_float2(t1.x - t3.y, t1.y + t3.x);   // t1 + i*t3
}

// 16-point forward DFT, natural input order. Output X[m] ends at slot PERM16(m).
__device__ __forceinline__ void dft16(float2 v[16]) {
    #pragma unroll
    for (int j0 = 0; j0 < 4; j0++) dft4(v[j0], v[j0 + 4], v[j0 + 8], v[j0 + 12]);
    const float C1 = 0.92387953251128675613f;   // cos(pi/8)
    const float S1 = 0.38268343236508977173f;   // sin(pi/8)
    const float C2 = 0.70710678118654752440f;   // sqrt(2)/2
    v[5]  = cmul(v[5],  make_float2( C1, -S1));
    v[9]  = cmul(v[9],  make_float2( C2, -C2));
    v[13] = cmul(v[13], make_float2( S1, -C1));
    v[6]  = cmul(v[6],  make_float2( C2, -C2));
    { float2 t = v[10]; v[10] = make_float2(t.y, -t.x); }
    v[14] = cmul(v[14], make_float2(-C2, -C2));
    v[7]  = cmul(v[7],  make_float2( S1, -C1));
    v[11] = cmul(v[11], make_float2(-C2, -C2));
    v[15] = cmul(v[15], make_float2(-C1,  S1));
    #pragma unroll
    for (int m0 = 0; m0 < 4; m0++) dft4(v[4*m0], v[4*m0+1], v[4*m0+2], v[4*m0+3]);
}

// Middle forward radix-16 DIF pass, Q = 16 (sub-transform length 256).
__device__ __forceinline__ void fwd_pass_mid(float2 *sm, const float2 *tw, int tid) {
    const int QP = 17;                 // PHYS stride for Q=16
    float2 *Bp = sm + (tid >> 8) * CST;
    int wi = tid & 255;
    int j  = wi & 15;
    int g  = wi >> 4;
    int p0 = PHYS(g * 256 + j);
    float2 v[16];
    #pragma unroll
    for (int m = 0; m < 16; m++) v[m] = Bp[p0 + m * QP];
    dft16(v);
    float2 w1 = tw[PHYT(j << 4)];
    Bp[p0] = v[0];
    Bp[p0 + QP] = cmul(v[PERM16(1)], w1);
    float2 w = w1;
    #pragma unroll
    for (int m = 2; m < 16; m++) {
        w = cmul(w, w1);
        Bp[p0 + m * QP] = cmul(v[PERM16(m)], w);
    }
    __syncthreads();
}

// Middle inverse radix-16 DIT pass, Q = 16.
__device__ __forceinline__ void inv_pass_mid(float2 *sm, const float2 *tw, int tid) {
    const int QP = 17;
    float2 *Bp = sm + (tid >> 8) * CST;
    int wi = tid & 255;
    int j  = wi & 15;
    int g  = wi >> 4;
    int p0 = PHYS(g * 256 + j);
    float2 w1 = tw[PHYT(j << 4)];
    float2 v[16];
    {
        float2 u = Bp[p0];
        v[0] = make_float2(u.x, -u.y);
    }
    v[1] = cmulc(w1, Bp[p0 + QP]);
    float2 w = w1;
    #pragma unroll
    for (int m = 2; m < 16; m++) {
        w = cmul(w, w1);
        v[m] = cmulc(w, Bp[p0 + m * QP]);
    }
    dft16(v);
    #pragma unroll
    for (int m = 0; m < 16; m++) {
        float2 u = v[PERM16(m)];
        Bp[p0 + m * QP] = make_float2(u.x, -u.y);
    }
    __syncthreads();
}

// Digit reversal for radices [16,16,16] DIF order (12-bit index).
__device__ __forceinline__ int rev16(int k) {
    return ((k & 15) << 8) | (k & 0xF0) | (k >> 8);
}

// Prologue: build PQRS coefficient pack. H row staged through smem so global
// reads are coalesced; scatter happens in LDS.
__global__ __launch_bounds__(1024) void _permute_H_kernel(const float2 *__restrict__ H2) {
    __shared__ float2 sh[4097];
    const int f = blockIdx.x;
    const float2 *Hb = H2 + (size_t)f * 4097;
    for (int i = threadIdx.x; i < 4097; i += 1024) sh[i] = __ldg(Hb + i);
    __syncthreads();
    float4 *out = g_Hpack + (size_t)f * 4096;
    for (int it = 0; it < 2; it++) {
        int q = it * 1024 + threadIdx.x;
        if (q == 0) {
            float2 hM = sh[2048];
            out[0] = make_float4(sh[0].x, sh[4096].x, hM.x, -hM.y);
            out[1] = make_float4(0.f, 0.f, 0.f, 0.f);
        } else {
            int k = ((q & 7) << 8) | (((q >> 3) & 15) << 4) | (q >> 7);
            float2 Hk = sh[k];
            float2 Hm = sh[4096 - k];
            float s, co;
            sincospif((float)k * (1.0f / 4096.0f), &s, &co);
            // W = (co, -s); a = (1-iW)/2; b = (1+iW)/2
            float aa = 0.5f * (1.0f - s);   // |a|^2
            float bb = 0.5f * (1.0f + s);   // |b|^2
            float ci = 0.5f * co;           // c = conj(a)*b = i*ci
            // P = aa*Hk + bb*conj(Hm)
            float2 P = make_float2(aa * Hk.x + bb * Hm.x, aa * Hk.y - bb * Hm.y);
            // Q = i*ci*(Hk - conj(Hm)) = (-ci*(Hk.y + Hm.y), ci*(Hk.x - Hm.x))
            float2 Q = make_float2(-ci * (Hk.y + Hm.y), ci * (Hk.x - Hm.x));
            // R = i*ci*(conj(Hk) - Hm) = ( ci*(Hk.y + Hm.y), ci*(Hk.x - Hm.x))
            float2 R = make_float2( ci * (Hk.y + Hm.y), ci * (Hk.x - Hm.x));
            // S = bb*conj(Hk) + aa*Hm
            float2 S = make_float2(bb * Hk.x + aa * Hm.x, -bb * Hk.y + aa * Hm.y);
            out[2 * q]     = make_float4(P.x, P.y, Q.x, Q.y);
            out[2 * q + 1] = make_float4(R.x, R.y, S.x, S.y);
        }
    }
}

__global__ __launch_bounds__(TPB, 1)
void _ScaleFFTFilter_45380624449589_kernel(const float *__restrict__ x,
                                           float *__restrict__ y) {
    extern __shared__ float2 smem_raw[];
    float2 *sm = smem_raw;             // 4 columns * CST
    float2 *tw = smem_raw + 4 * CST;   // padded twiddle table

    const int tid = threadIdx.x;
    const int fg  = blockIdx.x >> 3;   // feature group (0..127)
    const int b   = blockIdx.x & 7;    // batch (0..7)
    const int f0  = fg * 4;

    // twiddle table: tw[m] = e^{-2*pi*i*m/4096}, m < 256
    if (tid < TWN) {
        float s, co;
        sincospif((float)tid * (1.0f / 2048.0f), &s, &co);
        tw[PHYT(tid)] = make_float2(co, -s);
    }
    __syncthreads();

    // ---- fused: global load + pack + first fwd radix-16 pass (Q=256) ----
    {
        const int cc = tid & 3;
        const int j  = tid >> 2;       // 0..255
        const float *xc = x + ((size_t)b * 8192) * 512 + f0 + cc;
        float2 v[16];
        #pragma unroll
        for (int m = 0; m < 16; m++) {
            size_t row = (size_t)2 * (j + m * 256);
            v[m] = make_float2(__ldg(xc + row * 512), __ldg(xc + (row + 1) * 512));
        }
        dft16(v);
        float2 *Bp = sm + cc * CST;
        int p0 = PHYS(j);
        float2 w1 = tw[PHYT(j)];
        Bp[p0] = v[0];
        Bp[p0 + 272] = cmul(v[PERM16(1)], w1);
        float2 w = w1;
        #pragma unroll
        for (int m = 2; m < 16; m++) {
            w = cmul(w, w1);
            Bp[p0 + m * 272] = cmul(v[PERM16(m)], w);
        }
    }
    __syncthreads();

    fwd_pass_mid(sm, tw, tid);

    {   // final forward radix-16 blocks (no twiddles)
        float2 *Bp = sm + (tid >> 8) * CST;
        int p0 = PHYS((tid & 255) * 16);
        float2 v[16];
        #pragma unroll
        for (int j = 0; j < 16; j++) v[j] = Bp[p0 + j];
        dft16(v);
        #pragma unroll
        for (int m = 0; m < 16; m++) Bp[p0 + m] = v[PERM16(m)];
    }
    __syncthreads();

    // ---- filter: Zk' = P*Zk + Q*conj(Zm); Zm' = R*conj(Zk) + S*Zm ----
    for (int it = 0; it < 8; it++) {
        int idx = it * TPB + tid;      // 0..8191
        int cc = idx >> 11;
        int q  = idx & 2047;
        float2 *Bp = sm + cc * CST;
        const float4 *Hp = g_Hpack + (size_t)(f0 + cc) * 4096;
        float4 h1 = __ldg(Hp + 2 * q);
        if (q == 0) {
            // bins 0 / 4096 (packed in slot 0) and self-paired bin 2048
            float2 z0 = Bp[PHYS(0)];
            float Y0 = (z0.x + z0.y) * h1.x;
            float YN = (z0.x - z0.y) * h1.y;
            Bp[PHYS(0)] = make_float2(0.5f * (Y0 + YN), 0.5f * (Y0 - YN));
            float2 z2 = Bp[8];   // PHYS(rev16(2048)) = 8
            Bp[8] = cmul(z2, make_float2(h1.z, h1.w));   // * conj(H2048)
        } else {
            float4 h2 = __ldg(Hp + 2 * q + 1);
            int k = ((q & 7) << 8) | (((q >> 3) & 15) << 4) | (q >> 7);
            int pk = PHYS(rev16(k));
            int pm = PHYS(rev16(4096 - k));
            float2 Zk = Bp[pk];
            float2 Zm = Bp[pm];
            // P*Zk + Q*conj(Zm)
            Bp[pk] = make_float2(
                fmaf(h1.x, Zk.x, -h1.y * Zk.y) + fmaf(h1.z, Zm.x,  h1.w * Zm.y),
                fmaf(h1.x, Zk.y,  h1.y * Zk.x) + fmaf(h1.w, Zm.x, -h1.z * Zm.y));
            // R*conj(Zk) + S*Zm
            Bp[pm] = make_float2(
                fmaf(h2.x, Zk.x,  h2.y * Zk.y) + fmaf(h2.z, Zm.x, -h2.w * Zm.y),
                fmaf(h2.y, Zk.x, -h2.x * Zk.y) + fmaf(h2.z, Zm.y,  h2.w * Zm.x));
        }
    }
    __syncthreads();

    {   // first inverse radix-16 blocks (no twiddles)
        float2 *Bp = sm + (tid >> 8) * CST;
        int p0 = PHYS((tid & 255) * 16);
        float2 v[16];
        #pragma unroll
        for (int j = 0; j < 16; j++) {
            float2 u = Bp[p0 + j];
            v[j] = make_float2(u.x, -u.y);
        }
        dft16(v);
        #pragma unroll
        for (int m = 0; m < 16; m++) {
            float2 u = v[PERM16(m)];
            Bp[p0 + m] = make_float2(u.x, -u.y);
        }
    }
    __syncthreads();

    inv_pass_mid(sm, tw, tid);

    // ---- fused: last inverse pass (Q=256) + unpack + global store ----
    {
        const int cc = tid & 3;
        const int j  = tid >> 2;       // 0..255
        float2 *Bp = sm + cc * CST;
        int p0 = PHYS(j);
        float2 w1 = tw[PHYT(j)];
        float2 v[16];
        {
            float2 u = Bp[p0];
            v[0] = make_float2(u.x, -u.y);
        }
        v[1] = cmulc(w1, Bp[p0 + 272]);
        float2 w = w1;
        #pragma unroll
        for (int m = 2; m < 16; m++) {
            w = cmul(w, w1);
            v[m] = cmulc(w, Bp[p0 + m * 272]);
        }
        dft16(v);
        float *yc = y + ((size_t)b * 8192) * 512 + f0 + cc;
        const float SC = 1.0f / 4096.0f;
        #pragma unroll
        for (int m = 0; m < 16; m++) {
            float2 u = v[PERM16(m)];           // result = conj(u)
            size_t row = (size_t)2 * (j + m * 256);
            yc[row * 512]       = u.x * SC;
            yc[(row + 1) * 512] = -u.y * SC;
        }
    }
}

extern "C" void kernel_launch(void* const* d_in, const int* in_sizes, int n_in,
                              void* d_out, int out_size) {
    (void)in_sizes; (void)n_in; (void)out_size;
    const float  *x  = (const float*)d_in[0];
    const float2 *H2 = (const float2*)d_in[1];
    float        *y  = (float*)d_out;

    _permute_H_kernel<<<512, 1024>>>(H2);

    const size_t smem_bytes = (size_t)(4 * CST + TWSZ) * sizeof(float2);  // ~141.7 KB
    cudaFuncSetAttribute(_ScaleFFTFilter_45380624449589_kernel,
                         cudaFuncAttributeMaxDynamicSharedMemorySize,
                         (int)smem_bytes);
    _ScaleFFTFilter_45380624449589_kernel<<<1024, TPB, smem_bytes>>>(x, y);
}

// round 9
// speedup vs baseline: 1.0798x; 1.0798x over previous
#include <cuda_runtime.h>
#include <cuda_bf16.h>
#include <cstddef>

#define TPB      1024
#define NFFT     4096
#define CST      4356                 // per-column smem stride (float2)
#define PHYS(i)  ((i) + ((i) >> 4))   // data padding: every 16 elements
#define PHYT(i)  ((i) + ((i) >> 4) + ((i) >> 6))  // twiddle-table padding
#define TWN      256
#define TWSZ     288                  // > PHYT(255) = 273
#define PERM16(m) ((((m) & 3) << 2) | ((m) >> 2))

// Column-local barrier: 8 warps (256 threads) of one feature column.
#define BARCOL(c) asm volatile("bar.sync %0, 256;" :: "r"((c) + 1) : "memory")

// Scratch: filter as 2x2 complex linear map per (k, 4096-k) pair.
// Zk' = P*Zk + Q*conj(Zm); Zm' = R*conj(Zk) + S*Zm with R = -conj(Q).
// g_HpackPQ[f*2048+q] = (P.x,P.y,Q.x,Q.y); g_HpackS[f*2048+q] = (S.x,S.y).
// q==0 special: PQ slot 0 = (H0.re, HN.re, conjH2048.x, conjH2048.y).
__device__ float4 g_HpackPQ[512 * 2048];
__device__ float2 g_HpackS[512 * 2048];

__device__ __forceinline__ float2 cmul(float2 a, float2 b) {
    return make_float2(fmaf(a.x, b.x, -a.y * b.y), fmaf(a.x, b.y, a.y * b.x));
}
// a * conj(b)
__device__ __forceinline__ float2 cmulc(float2 a, float2 b) {
    return make_float2(fmaf(a.x, b.x, a.y * b.y), fmaf(a.y, b.x, -a.x * b.y));
}

__device__ __forceinline__ void dft4(float2 &a, float2 &b, float2 &c, float2 &d) {
    float2 t0 = make_float2(a.x + c.x, a.y + c.y);
    float2 t1 = make_float2(a.x - c.x, a.y - c.y);
    float2 t2 = make_float2(b.x + d.x, b.y + d.y);
    float2 t3 = make_float2(b.x - d.x, b.y - d.y);
    a = make_float2(t0.x + t2.x, t0.y + t2.y);
    c = make_float2(t0.x - t2.x, t0.y - t2.y);
    b = make_float2(t1.x + t3.y, t1.y - t3.x);   // t1 - i*t3
    d = make_float2(t1.x - t3.y, t1.y + t3.x);   // t1 + i*t3
}

// 16-point forward DFT, natural input order. Output X[m] ends at slot PERM16(m).
__device__ __forceinline__ void dft16(float2 v[16]) {
    #pragma unroll
    for (int j0 = 0; j0 < 4; j0++) dft4(v[j0], v[j0 + 4], v[j0 + 8], v[j0 + 12]);
    const float C1 = 0.92387953251128675613f;   // cos(pi/8)
    const float S1 = 0.38268343236508977173f;   // sin(pi/8)
    const float C2 = 0.70710678118654752440f;   // sqrt(2)/2
    v[5]  = cmul(v[5],  make_float2( C1, -S1));
    v[9]  = cmul(v[9],  make_float2( C2, -C2));
    v[13] = cmul(v[13], make_float2( S1, -C1));
    v[6]  = cmul(v[6],  make_float2( C2, -C2));
    { float2 t = v[10]; v[10] = make_float2(t.y, -t.x); }
    v[14] = cmul(v[14], make_float2(-C2, -C2));
    v[7]  = cmul(v[7],  make_float2( S1, -C1));
    v[11] = cmul(v[11], make_float2(-C2, -C2));
    v[15] = cmul(v[15], make_float2(-C1,  S1));
    #pragma unroll
    for (int m0 = 0; m0 < 4; m0++) dft4(v[4*m0], v[4*m0+1], v[4*m0+2], v[4*m0+3]);
}

// Digit reversal for radices [16,16,16] DIF order (12-bit index).
__device__ __forceinline__ int rev16(int k) {
    return ((k & 15) << 8) | (k & 0xF0) | (k >> 8);
}

// Prologue: build coefficient pack. H row staged through smem so global reads
// are coalesced; scatter happens in LDS. Outputs are lane-coalesced.
__global__ __launch_bounds__(1024) void _permute_H_kernel(const float2 *__restrict__ H2) {
    __shared__ float2 sh[4097];
    const int f = blockIdx.x;
    const float2 *Hb = H2 + (size_t)f * 4097;
    for (int i = threadIdx.x; i < 4097; i += 1024) sh[i] = __ldg(Hb + i);
    __syncthreads();
    float4 *outPQ = g_HpackPQ + (size_t)f * 2048;
    float2 *outS  = g_HpackS  + (size_t)f * 2048;
    for (int it = 0; it < 2; it++) {
        int q = it * 1024 + threadIdx.x;
        if (q == 0) {
            float2 hM = sh[2048];
            outPQ[0] = make_float4(sh[0].x, sh[4096].x, hM.x, -hM.y);
            outS[0]  = make_float2(0.f, 0.f);
        } else {
            int k = ((q & 7) << 8) | (((q >> 3) & 15) << 4) | (q >> 7);
            float2 Hk = sh[k];
            float2 Hm = sh[4096 - k];
            float s, co;
            sincospif((float)k * (1.0f / 4096.0f), &s, &co);
            float aa = 0.5f * (1.0f - s);
            float bb = 0.5f * (1.0f + s);
            float ci = 0.5f * co;
            float2 P = make_float2(aa * Hk.x + bb * Hm.x, aa * Hk.y - bb * Hm.y);
            float2 Q = make_float2(-ci * (Hk.y + Hm.y), ci * (Hk.x - Hm.x));
            float2 S = make_float2(bb * Hk.x + aa * Hm.x, -bb * Hk.y + aa * Hm.y);
            outPQ[q] = make_float4(P.x, P.y, Q.x, Q.y);
            outS[q]  = S;
        }
    }
}

__global__ __launch_bounds__(TPB, 1)
void _ScaleFFTFilter_45380624449589_kernel(const float *__restrict__ x,
                                           float *__restrict__ y) {
    extern __shared__ float2 smem_raw[];
    float2 *sm = smem_raw;             // 4 columns * CST
    float2 *tw = smem_raw + 4 * CST;   // padded twiddle table

    const int tid = threadIdx.x;
    const int fg  = blockIdx.x >> 3;   // feature group (0..127)
    const int b   = blockIdx.x & 7;    // batch (0..7)
    const int f0  = fg * 4;
    const int col = tid >> 8;          // column owned in the middle phases
    const int u   = tid & 255;

    // twiddle table: tw[m] = e^{-2*pi*i*m/4096}, m < 256
    if (tid < TWN) {
        float s, co;
        sincospif((float)tid * (1.0f / 2048.0f), &s, &co);
        tw[PHYT(tid)] = make_float2(co, -s);
    }
    __syncthreads();

    // ---- fused: global load + pack + first fwd radix-16 pass (Q=256) ----
    // cc = tid&3 so each warp covers 4 cols x 8 rows (16B/sector coalescing).
    {
        const int cc = tid & 3;
        const int j  = tid >> 2;       // 0..255
        const float *xc = x + ((size_t)b * 8192) * 512 + f0 + cc;
        float2 v[16];
        #pragma unroll
        for (int m = 0; m < 16; m++) {
            size_t row = (size_t)2 * (j + m * 256);
            v[m] = make_float2(__ldg(xc + row * 512), __ldg(xc + (row + 1) * 512));
        }
        dft16(v);
        float2 *Bp = sm + cc * CST;
        int p0 = PHYS(j);
        float2 w1 = tw[PHYT(j)];
        Bp[p0] = v[0];
        Bp[p0 + 272] = cmul(v[PERM16(1)], w1);
        float2 w = w1;
        #pragma unroll
        for (int m = 2; m < 16; m++) {
            w = cmul(w, w1);
            Bp[p0 + m * 272] = cmul(v[PERM16(m)], w);
        }
    }
    __syncthreads();

    // ---- middle fwd radix-16 pass, Q=16 (column-local) ----
    {
        float2 *Bp = sm + col * CST;
        int j = u & 15;
        int g = u >> 4;
        int p0 = PHYS(g * 256 + j);
        float2 v[16];
        #pragma unroll
        for (int m = 0; m < 16; m++) v[m] = Bp[p0 + m * 17];
        dft16(v);
        float2 w1 = tw[PHYT(j << 4)];
        Bp[p0] = v[0];
        Bp[p0 + 17] = cmul(v[PERM16(1)], w1);
        float2 w = w1;
        #pragma unroll
        for (int m = 2; m < 16; m++) {
            w = cmul(w, w1);
            Bp[p0 + m * 17] = cmul(v[PERM16(m)], w);
        }
    }
    BARCOL(col);

    {   // final forward radix-16 blocks (no twiddles, column-local)
        float2 *Bp = sm + col * CST;
        int p0 = PHYS(u * 16);
        float2 v[16];
        #pragma unroll
        for (int j = 0; j < 16; j++) v[j] = Bp[p0 + j];
        dft16(v);
        #pragma unroll
        for (int m = 0; m < 16; m++) Bp[p0 + m] = v[PERM16(m)];
    }
    BARCOL(col);

    // ---- filter (column-local): Zk' = P*Zk + Q*conj(Zm);
    //      Zm' = R*conj(Zk) + S*Zm with R = (-Q.x, Q.y) ----
    {
        float2 *Bp = sm + col * CST;
        const float4 *Hpq = g_HpackPQ + (size_t)(f0 + col) * 2048;
        const float2 *Hs  = g_HpackS  + (size_t)(f0 + col) * 2048;
        #pragma unroll
        for (int it = 0; it < 8; it++) {
            int q = it * 256 + u;
            float4 h1 = __ldg(Hpq + q);
            if (q == 0) {
                // bins 0 / 4096 (packed) and self-paired bin 2048
                float2 z0 = Bp[0];
                float Y0 = (z0.x + z0.y) * h1.x;
                float YN = (z0.x - z0.y) * h1.y;
                Bp[0] = make_float2(0.5f * (Y0 + YN), 0.5f * (Y0 - YN));
                float2 z2 = Bp[8];   // PHYS(rev16(2048)) = 8
                Bp[8] = cmul(z2, make_float2(h1.z, h1.w));   // * conj(H2048)
            } else {
                float2 s2 = __ldg(Hs + q);
                int k = ((q & 7) << 8) | (((q >> 3) & 15) << 4) | (q >> 7);
                int pk = PHYS(rev16(k));
                int pm = PHYS(rev16(4096 - k));
                float2 Zk = Bp[pk];
                float2 Zm = Bp[pm];
                Bp[pk] = make_float2(
                    fmaf(h1.x, Zk.x, -h1.y * Zk.y) + fmaf(h1.z, Zm.x,  h1.w * Zm.y),
                    fmaf(h1.x, Zk.y,  h1.y * Zk.x) + fmaf(h1.w, Zm.x, -h1.z * Zm.y));
                Bp[pm] = make_float2(
                    fmaf(-h1.z, Zk.x, h1.w * Zk.y) + fmaf(s2.x, Zm.x, -s2.y * Zm.y),
                    fmaf( h1.w, Zk.x, h1.z * Zk.y) + fmaf(s2.x, Zm.y,  s2.y * Zm.x));
            }
        }
    }
    BARCOL(col);

    {   // first inverse radix-16 blocks (no twiddles, column-local)
        float2 *Bp = sm + col * CST;
        int p0 = PHYS(u * 16);
        float2 v[16];
        #pragma unroll
        for (int j = 0; j < 16; j++) {
            float2 w = Bp[p0 + j];
            v[j] = make_float2(w.x, -w.y);
        }
        dft16(v);
        #pragma unroll
        for (int m = 0; m < 16; m++) {
            float2 w = v[PERM16(m)];
            Bp[p0 + m] = make_float2(w.x, -w.y);
        }
    }
    BARCOL(col);

    // ---- middle inverse radix-16 pass, Q=16 (column-local) ----
    {
        float2 *Bp = sm + col * CST;
        int j = u & 15;
        int g = u >> 4;
        int p0 = PHYS(g * 256 + j);
        float2 w1 = tw[PHYT(j << 4)];
        float2 v[16];
        {
            float2 w = Bp[p0];
            v[0] = make_float2(w.x, -w.y);
        }
        v[1] = cmulc(w1, Bp[p0 + 17]);
        float2 w = w1;
        #pragma unroll
        for (int m = 2; m < 16; m++) {
            w = cmul(w, w1);
            v[m] = cmulc(w, Bp[p0 + m * 17]);
        }
        dft16(v);
        #pragma unroll
        for (int m = 0; m < 16; m++) {
            float2 t = v[PERM16(m)];
            Bp[p0 + m * 17] = make_float2(t.x, -t.y);
        }
    }
    __syncthreads();   // next phase reads across columns

    // ---- fused: last inverse pass (Q=256) + unpack + global store ----
    {
        const int cc = tid & 3;
        const int j  = tid >> 2;       // 0..255
        float2 *Bp = sm + cc * CST;
        int p0 = PHYS(j);
        float2 w1 = tw[PHYT(j)];
        float2 v[16];
        {
            float2 t = Bp[p0];
            v[0] = make_float2(t.x, -t.y);
        }
        v[1] = cmulc(w1, Bp[p0 + 272]);
        float2 w = w1;
        #pragma unroll
        for (int m = 2; m < 16; m++) {
            w = cmul(w, w1);
            v[m] = cmulc(w, Bp[p0 + m * 272]);
        }
        dft16(v);
        float *yc = y + ((size_t)b * 8192) * 512 + f0 + cc;
        const float SC = 1.0f / 4096.0f;
        #pragma unroll
        for (int m = 0; m < 16; m++) {
            float2 t = v[PERM16(m)];           // result = conj(t)
            size_t row = (size_t)2 * (j + m * 256);
            yc[row * 512]       = t.x * SC;
            yc[(row + 1) * 512] = -t.y * SC;
        }
    }
}

extern "C" void kernel_launch(void* const* d_in, const int* in_sizes, int n_in,
                              void* d_out, int out_size) {
    (void)in_sizes; (void)n_in; (void)out_size;
    const float  *x  = (const float*)d_in[0];
    const float2 *H2 = (const float2*)d_in[1];
    float        *y  = (float*)d_out;

    _permute_H_kernel<<<512, 1024>>>(H2);

    const size_t smem_bytes = (size_t)(4 * CST + TWSZ) * sizeof(float2);  // ~141.7 KB
    cudaFuncSetAttribute(_ScaleFFTFilter_45380624449589_kernel,
                         cudaFuncAttributeMaxDynamicSharedMemorySize,
                         (int)smem_bytes);
    _ScaleFFTFilter_45380624449589_kernel<<<1024, TPB, smem_bytes>>>(x, y);
}

// round 10
// speedup vs baseline: 1.1259x; 1.0426x over previous
#include <cuda_runtime.h>
#include <cuda_bf16.h>
#include <cstddef>

#define TPB      1024
#define NFFT     4096
#define CST      4356                 // per-column smem stride (float2)
#define PHYS(i)  ((i) + ((i) >> 4))   // data padding: every 16 elements
#define PHYT(i)  ((i) + ((i) >> 4) + ((i) >> 6))  // twiddle-table padding
#define TWN      256
#define TWSZ     288                  // > PHYT(255) = 273
#define PERM16(m) ((((m) & 3) << 2) | ((m) >> 2))
// Prologue staging pad: lanes read k + {256a + 16b}; this pad spreads banks.
#define SHP(i)   ((i) + ((i) >> 4) + ((i) >> 7))

// Column-local barrier: 8 warps (256 threads) of one feature column.
#define BARCOL(c) asm volatile("bar.sync %0, 256;" :: "r"((c) + 1) : "memory")

// Scratch: filter as 2x2 complex linear map per (k, 4096-k) pair.
// Zk' = P*Zk + Q*conj(Zm); Zm' = R*conj(Zk) + S*Zm with R = -conj(Q).
// g_HpackPQ[f*2048+q] = (P.x,P.y,Q.x,Q.y); g_HpackS[f*2048+q] = (S.x,S.y).
// q==0 special: PQ slot 0 = (H0.re, HN.re, conjH2048.x, conjH2048.y).
__device__ float4 g_HpackPQ[512 * 2048];
__device__ float2 g_HpackS[512 * 2048];

__device__ __forceinline__ float2 cmul(float2 a, float2 b) {
    return make_float2(fmaf(a.x, b.x, -a.y * b.y), fmaf(a.x, b.y, a.y * b.x));
}
// a * conj(b)
__device__ __forceinline__ float2 cmulc(float2 a, float2 b) {
    return make_float2(fmaf(a.x, b.x, a.y * b.y), fmaf(a.y, b.x, -a.x * b.y));
}

__device__ __forceinline__ void dft4(float2 &a, float2 &b, float2 &c, float2 &d) {
    float2 t0 = make_float2(a.x + c.x, a.y + c.y);
    float2 t1 = make_float2(a.x - c.x, a.y - c.y);
    float2 t2 = make_float2(b.x + d.x, b.y + d.y);
    float2 t3 = make_float2(b.x - d.x, b.y - d.y);
    a = make_float2(t0.x + t2.x, t0.y + t2.y);
    c = make_float2(t0.x - t2.x, t0.y - t2.y);
    b = make_float2(t1.x + t3.y, t1.y - t3.x);   // t1 - i*t3
    d = make_float2(t1.x - t3.y, t1.y + t3.x);   // t1 + i*t3
}

// 16-point forward DFT, natural input order. Output X[m] ends at slot PERM16(m).
__device__ __forceinline__ void dft16(float2 v[16]) {
    #pragma unroll
    for (int j0 = 0; j0 < 4; j0++) dft4(v[j0], v[j0 + 4], v[j0 + 8], v[j0 + 12]);
    const float C1 = 0.92387953251128675613f;   // cos(pi/8)
    const float S1 = 0.38268343236508977173f;   // sin(pi/8)
    const float C2 = 0.70710678118654752440f;   // sqrt(2)/2
    v[5]  = cmul(v[5],  make_float2( C1, -S1));
    v[9]  = cmul(v[9],  make_float2( C2, -C2));
    v[13] = cmul(v[13], make_float2( S1, -C1));
    v[6]  = cmul(v[6],  make_float2( C2, -C2));
    { float2 t = v[10]; v[10] = make_float2(t.y, -t.x); }
    v[14] = cmul(v[14], make_float2(-C2, -C2));
    v[7]  = cmul(v[7],  make_float2( S1, -C1));
    v[11] = cmul(v[11], make_float2(-C2, -C2));
    v[15] = cmul(v[15], make_float2(-C1,  S1));
    #pragma unroll
    for (int m0 = 0; m0 < 4; m0++) dft4(v[4*m0], v[4*m0+1], v[4*m0+2], v[4*m0+3]);
}

// Digit reversal for radices [16,16,16] DIF order (12-bit index).
__device__ __forceinline__ int rev16(int k) {
    return ((k & 15) << 8) | (k & 0xF0) | (k >> 8);
}

// Twiddled store phase: dual even/odd chains (depth 7 each, not 14).
template <int QP>
__device__ __forceinline__ void store_twiddled(float2 *Bp, int p0, float2 v[16], float2 w1) {
    float2 w2 = cmul(w1, w1);
    Bp[p0] = v[0];
    Bp[p0 + QP] = cmul(v[PERM16(1)], w1);
    Bp[p0 + 2 * QP] = cmul(v[PERM16(2)], w2);
    float2 wo = w1;
    float2 we = w2;
    #pragma unroll
    for (int m = 3; m < 16; m += 2) {
        wo = cmul(wo, w2);
        Bp[p0 + m * QP] = cmul(v[PERM16(m)], wo);
    }
    #pragma unroll
    for (int m = 4; m < 16; m += 2) {
        we = cmul(we, w2);
        Bp[p0 + m * QP] = cmul(v[PERM16(m)], we);
    }
}

// Twiddled (conjugate) load phase for inverse passes, dual chains.
// v[m] = conj(raw * conj(w^m)) = cmulc(w^m, raw).
template <int QP>
__device__ __forceinline__ void load_twiddled_conj(const float2 *Bp, int p0, float2 v[16], float2 w1) {
    float2 w2 = cmul(w1, w1);
    {
        float2 u = Bp[p0];
        v[0] = make_float2(u.x, -u.y);
    }
    v[1] = cmulc(w1, Bp[p0 + QP]);
    v[2] = cmulc(w2, Bp[p0 + 2 * QP]);
    float2 wo = w1;
    float2 we = w2;
    #pragma unroll
    for (int m = 3; m < 16; m += 2) {
        wo = cmul(wo, w2);
        v[m] = cmulc(wo, Bp[p0 + m * QP]);
    }
    #pragma unroll
    for (int m = 4; m < 16; m += 2) {
        we = cmul(we, w2);
        v[m] = cmulc(we, Bp[p0 + m * QP]);
    }
}

// Prologue: build coefficient pack. H row staged through padded smem so both
// the global reads (coalesced) and the LDS scatter (<=2-way banks) are cheap.
__global__ __launch_bounds__(1024) void _permute_H_kernel(const float2 *__restrict__ H2) {
    __shared__ float2 sh[SHP(4096) + 8];
    const int f = blockIdx.x;
    const float2 *Hb = H2 + (size_t)f * 4097;
    for (int i = threadIdx.x; i < 4097; i += 1024) sh[SHP(i)] = __ldg(Hb + i);
    __syncthreads();
    float4 *outPQ = g_HpackPQ + (size_t)f * 2048;
    float2 *outS  = g_HpackS  + (size_t)f * 2048;
    for (int it = 0; it < 2; it++) {
        int q = it * 1024 + threadIdx.x;
        if (q == 0) {
            float2 hM = sh[SHP(2048)];
            outPQ[0] = make_float4(sh[SHP(0)].x, sh[SHP(4096)].x, hM.x, -hM.y);
            outS[0]  = make_float2(0.f, 0.f);
        } else {
            int k = ((q & 7) << 8) | (((q >> 3) & 15) << 4) | (q >> 7);
            float2 Hk = sh[SHP(k)];
            float2 Hm = sh[SHP(4096 - k)];
            float s, co;
            sincospif((float)k * (1.0f / 4096.0f), &s, &co);
            float aa = 0.5f * (1.0f - s);
            float bb = 0.5f * (1.0f + s);
            float ci = 0.5f * co;
            float2 P = make_float2(aa * Hk.x + bb * Hm.x, aa * Hk.y - bb * Hm.y);
            float2 Q = make_float2(-ci * (Hk.y + Hm.y), ci * (Hk.x - Hm.x));
            float2 S = make_float2(bb * Hk.x + aa * Hm.x, -bb * Hk.y + aa * Hm.y);
            outPQ[q] = make_float4(P.x, P.y, Q.x, Q.y);
            outS[q]  = S;
        }
    }
}

__global__ __launch_bounds__(TPB, 1)
void _ScaleFFTFilter_45380624449589_kernel(const float *__restrict__ x,
                                           float *__restrict__ y) {
    extern __shared__ float2 smem_raw[];
    float2 *sm = smem_raw;             // 4 columns * CST
    float2 *tw = smem_raw + 4 * CST;   // padded twiddle table

    const int tid = threadIdx.x;
    const int fg  = blockIdx.x >> 3;   // feature group (0..127)
    const int b   = blockIdx.x & 7;    // batch (0..7)
    const int f0  = fg * 4;
    const int col = tid >> 8;          // column owned in the middle phases
    const int u   = tid & 255;

    // twiddle table: tw[m] = e^{-2*pi*i*m/4096}, m < 256
    if (tid < TWN) {
        float s, co;
        sincospif((float)tid * (1.0f / 2048.0f), &s, &co);
        tw[PHYT(tid)] = make_float2(co, -s);
    }
    __syncthreads();

    // ---- fused: global load + pack + first fwd radix-16 pass (Q=256) ----
    {
        const int cc = tid & 3;
        const int j  = tid >> 2;       // 0..255
        const float *xc = x + ((size_t)b * 8192) * 512 + f0 + cc;
        float2 v[16];
        #pragma unroll
        for (int m = 0; m < 16; m++) {
            size_t row = (size_t)2 * (j + m * 256);
            v[m] = make_float2(__ldg(xc + row * 512), __ldg(xc + (row + 1) * 512));
        }
        dft16(v);
        store_twiddled<272>(sm + cc * CST, PHYS(j), v, tw[PHYT(j)]);
    }
    __syncthreads();

    // ---- middle fwd radix-16 pass, Q=16 (column-local) ----
    {
        float2 *Bp = sm + col * CST;
        int j = u & 15;
        int g = u >> 4;
        int p0 = PHYS(g * 256 + j);
        float2 v[16];
        #pragma unroll
        for (int m = 0; m < 16; m++) v[m] = Bp[p0 + m * 17];
        dft16(v);
        store_twiddled<17>(Bp, p0, v, tw[PHYT(j << 4)]);
    }
    BARCOL(col);

    {   // final forward radix-16 blocks (no twiddles, column-local)
        float2 *Bp = sm + col * CST;
        int p0 = PHYS(u * 16);
        float2 v[16];
        #pragma unroll
        for (int j = 0; j < 16; j++) v[j] = Bp[p0 + j];
        dft16(v);
        #pragma unroll
        for (int m = 0; m < 16; m++) Bp[p0 + m] = v[PERM16(m)];
    }
    BARCOL(col);

    // ---- filter (column-local): Zk' = P*Zk + Q*conj(Zm);
    //      Zm' = R*conj(Zk) + S*Zm with R = (-Q.x, Q.y) ----
    {
        float2 *Bp = sm + col * CST;
        const float4 *Hpq = g_HpackPQ + (size_t)(f0 + col) * 2048;
        const float2 *Hs  = g_HpackS  + (size_t)(f0 + col) * 2048;
        #pragma unroll
        for (int it = 0; it < 8; it++) {
            int q = it * 256 + u;
            float4 h1 = __ldg(Hpq + q);
            if (q == 0) {
                float2 z0 = Bp[0];
                float Y0 = (z0.x + z0.y) * h1.x;
                float YN = (z0.x - z0.y) * h1.y;
                Bp[0] = make_float2(0.5f * (Y0 + YN), 0.5f * (Y0 - YN));
                float2 z2 = Bp[8];   // PHYS(rev16(2048)) = 8
                Bp[8] = cmul(z2, make_float2(h1.z, h1.w));   // * conj(H2048)
            } else {
                float2 s2 = __ldg(Hs + q);
                int k = ((q & 7) << 8) | (((q >> 3) & 15) << 4) | (q >> 7);
                int pk = PHYS(rev16(k));
                int pm = PHYS(rev16(4096 - k));
                float2 Zk = Bp[pk];
                float2 Zm = Bp[pm];
                Bp[pk] = make_float2(
                    fmaf(h1.x, Zk.x, -h1.y * Zk.y) + fmaf(h1.z, Zm.x,  h1.w * Zm.y),
                    fmaf(h1.x, Zk.y,  h1.y * Zk.x) + fmaf(h1.w, Zm.x, -h1.z * Zm.y));
                Bp[pm] = make_float2(
                    fmaf(-h1.z, Zk.x, h1.w * Zk.y) + fmaf(s2.x, Zm.x, -s2.y * Zm.y),
                    fmaf( h1.w, Zk.x, h1.z * Zk.y) + fmaf(s2.x, Zm.y,  s2.y * Zm.x));
            }
        }
    }
    BARCOL(col);

    {   // first inverse radix-16 blocks (no twiddles, column-local)
        float2 *Bp = sm + col * CST;
        int p0 = PHYS(u * 16);
        float2 v[16];
        #pragma unroll
        for (int j = 0; j < 16; j++) {
            float2 w = Bp[p0 + j];
            v[j] = make_float2(w.x, -w.y);
        }
        dft16(v);
        #pragma unroll
        for (int m = 0; m < 16; m++) {
            float2 w = v[PERM16(m)];
            Bp[p0 + m] = make_float2(w.x, -w.y);
        }
    }
    BARCOL(col);

    // ---- middle inverse radix-16 pass, Q=16 (column-local) ----
    {
        float2 *Bp = sm + col * CST;
        int j = u & 15;
        int g = u >> 4;
        int p0 = PHYS(g * 256 + j);
        float2 v[16];
        load_twiddled_conj<17>(Bp, p0, v, tw[PHYT(j << 4)]);
        dft16(v);
        #pragma unroll
        for (int m = 0; m < 16; m++) {
            float2 t = v[PERM16(m)];
            Bp[p0 + m * 17] = make_float2(t.x, -t.y);
        }
    }
    __syncthreads();   // next phase reads across columns

    // ---- fused: last inverse pass (Q=256) + unpack + global store ----
    {
        const int cc = tid & 3;
        const int j  = tid >> 2;       // 0..255
        float2 *Bp = sm + cc * CST;
        float2 v[16];
        load_twiddled_conj<272>(Bp, PHYS(j), v, tw[PHYT(j)]);
        dft16(v);
        float *yc = y + ((size_t)b * 8192) * 512 + f0 + cc;
        const float SC = 1.0f / 4096.0f;
        #pragma unroll
        for (int m = 0; m < 16; m++) {
            float2 t = v[PERM16(m)];           // result = conj(t)
            size_t row = (size_t)2 * (j + m * 256);
            yc[row * 512]       = t.x * SC;
            yc[(row + 1) * 512] = -t.y * SC;
        }
    }
}

extern "C" void kernel_launch(void* const* d_in, const int* in_sizes, int n_in,
                              void* d_out, int out_size) {
    (void)in_sizes; (void)n_in; (void)out_size;
    const float  *x  = (const float*)d_in[0];
    const float2 *H2 = (const float2*)d_in[1];
    float        *y  = (float*)d_out;

    _permute_H_kernel<<<512, 1024>>>(H2);

    const size_t smem_bytes = (size_t)(4 * CST + TWSZ) * sizeof(float2);  // ~141.7 KB
    cudaFuncSetAttribute(_ScaleFFTFilter_45380624449589_kernel,
                         cudaFuncAttributeMaxDynamicSharedMemorySize,
                         (int)smem_bytes);
    _ScaleFFTFilter_45380624449589_kernel<<<1024, TPB, smem_bytes>>>(x, y);
}

// round 11
// speedup vs baseline: 1.1272x; 1.0012x over previous
#include <cuda_runtime.h>
#include <cuda_bf16.h>
#include <cstddef>

#define TPB      1024
#define NFFT     4096
#define CST      4356                 // per-column smem stride (float2)
#define PHYS(i)  ((i) + ((i) >> 4))   // data padding: every 16 elements
#define PHYT(i)  ((i) + ((i) >> 4) + ((i) >> 6))  // twiddle-table padding
#define TWN      256
#define TWSZ     288                  // > PHYT(255) = 273
#define PERM16(m) ((((m) & 3) << 2) | ((m) >> 2))
// Prologue staging pad: lanes read k + {256a + 16b}; this pad spreads banks.
#define SHP(i)   ((i) + ((i) >> 4) + ((i) >> 7))

// Column-local barrier: 8 warps (256 threads) of one feature column.
#define BARCOL(c) asm volatile("bar.sync %0, 256;" :: "r"((c) + 1) : "memory")

// Scratch: filter as 2x2 complex linear map per (k, 4096-k) pair.
// Zk' = P*Zk + Q*conj(Zm); Zm' = R*conj(Zk) + S*Zm with R = -conj(Q).
// g_HpackPQ[f*2048+q] = (P.x,P.y,Q.x,Q.y); g_HpackS[f*2048+q] = (S.x,S.y).
// q==0 special: PQ slot 0 = (H0.re, HN.re, conjH2048.x, conjH2048.y).
__device__ float4 g_HpackPQ[512 * 2048];
__device__ float2 g_HpackS[512 * 2048];

__device__ __forceinline__ float2 cmul(float2 a, float2 b) {
    return make_float2(fmaf(a.x, b.x, -a.y * b.y), fmaf(a.x, b.y, a.y * b.x));
}
// a * conj(b)
__device__ __forceinline__ float2 cmulc(float2 a, float2 b) {
    return make_float2(fmaf(a.x, b.x, a.y * b.y), fmaf(a.y, b.x, -a.x * b.y));
}

__device__ __forceinline__ void dft4(float2 &a, float2 &b, float2 &c, float2 &d) {
    float2 t0 = make_float2(a.x + c.x, a.y + c.y);
    float2 t1 = make_float2(a.x - c.x, a.y - c.y);
    float2 t2 = make_float2(b.x + d.x, b.y + d.y);
    float2 t3 = make_float2(b.x - d.x, b.y - d.y);
    a = make_float2(t0.x + t2.x, t0.y + t2.y);
    c = make_float2(t0.x - t2.x, t0.y - t2.y);
    b = make_float2(t1.x + t3.y, t1.y - t3.x);   // t1 - i*t3
    d = make_float2(t1.x - t3.y, t1.y + t3.x);   // t1 + i*t3
}

// 16-point forward DFT, natural input order. Output X[m] ends at slot PERM16(m).
__device__ __forceinline__ void dft16(float2 v[16]) {
    #pragma unroll
    for (int j0 = 0; j0 < 4; j0++) dft4(v[j0], v[j0 + 4], v[j0 + 8], v[j0 + 12]);
    const float C1 = 0.92387953251128675613f;   // cos(pi/8)
    const float S1 = 0.38268343236508977173f;   // sin(pi/8)
    const float C2 = 0.70710678118654752440f;   // sqrt(2)/2
    v[5]  = cmul(v[5],  make_float2( C1, -S1));
    v[9]  = cmul(v[9],  make_float2( C2, -C2));
    v[13] = cmul(v[13], make_float2( S1, -C1));
    v[6]  = cmul(v[6],  make_float2( C2, -C2));
    { float2 t = v[10]; v[10] = make_float2(t.y, -t.x); }
    v[14] = cmul(v[14], make_float2(-C2, -C2));
    v[7]  = cmul(v[7],  make_float2( S1, -C1));
    v[11] = cmul(v[11], make_float2(-C2, -C2));
    v[15] = cmul(v[15], make_float2(-C1,  S1));
    #pragma unroll
    for (int m0 = 0; m0 < 4; m0++) dft4(v[4*m0], v[4*m0+1], v[4*m0+2], v[4*m0+3]);
}

// Digit reversal for radices [16,16,16] DIF order (12-bit index).
__device__ __forceinline__ int rev16(int k) {
    return ((k & 15) << 8) | (k & 0xF0) | (k >> 8);
}

// Twiddled store phase: dual even/odd chains (depth 7 each, not 14).
template <int QP>
__device__ __forceinline__ void store_twiddled(float2 *Bp, int p0, float2 v[16], float2 w1) {
    float2 w2 = cmul(w1, w1);
    Bp[p0] = v[0];
    Bp[p0 + QP] = cmul(v[PERM16(1)], w1);
    Bp[p0 + 2 * QP] = cmul(v[PERM16(2)], w2);
    float2 wo = w1;
    float2 we = w2;
    #pragma unroll
    for (int m = 3; m < 16; m += 2) {
        wo = cmul(wo, w2);
        Bp[p0 + m * QP] = cmul(v[PERM16(m)], wo);
    }
    #pragma unroll
    for (int m = 4; m < 16; m += 2) {
        we = cmul(we, w2);
        Bp[p0 + m * QP] = cmul(v[PERM16(m)], we);
    }
}

// Twiddled (conjugate) load phase for inverse passes, dual chains.
// v[m] = conj(raw * conj(w^m)) = cmulc(w^m, raw).
template <int QP>
__device__ __forceinline__ void load_twiddled_conj(const float2 *Bp, int p0, float2 v[16], float2 w1) {
    float2 w2 = cmul(w1, w1);
    {
        float2 u = Bp[p0];
        v[0] = make_float2(u.x, -u.y);
    }
    v[1] = cmulc(w1, Bp[p0 + QP]);
    v[2] = cmulc(w2, Bp[p0 + 2 * QP]);
    float2 wo = w1;
    float2 we = w2;
    #pragma unroll
    for (int m = 3; m < 16; m += 2) {
        wo = cmul(wo, w2);
        v[m] = cmulc(wo, Bp[p0 + m * QP]);
    }
    #pragma unroll
    for (int m = 4; m < 16; m += 2) {
        we = cmul(we, w2);
        v[m] = cmulc(we, Bp[p0 + m * QP]);
    }
}

// Prologue: build coefficient pack. 512 threads/CTA so 4 CTAs/SM co-reside ->
// all 512 CTAs fit in ONE wave (previous 1024-thread version needed 2 waves).
__global__ __launch_bounds__(512) void _permute_H_kernel(const float2 *__restrict__ H2) {
    __shared__ float2 sh[SHP(4096) + 8];
    const int f = blockIdx.x;
    const float2 *Hb = H2 + (size_t)f * 4097;
    for (int i = threadIdx.x; i < 4097; i += 512) sh[SHP(i)] = __ldg(Hb + i);
    __syncthreads();
    float4 *outPQ = g_HpackPQ + (size_t)f * 2048;
    float2 *outS  = g_HpackS  + (size_t)f * 2048;
    #pragma unroll
    for (int it = 0; it < 4; it++) {
        int q = it * 512 + threadIdx.x;
        if (q == 0) {
            float2 hM = sh[SHP(2048)];
            outPQ[0] = make_float4(sh[SHP(0)].x, sh[SHP(4096)].x, hM.x, -hM.y);
            outS[0]  = make_float2(0.f, 0.f);
        } else {
            int k = ((q & 7) << 8) | (((q >> 3) & 15) << 4) | (q >> 7);
            float2 Hk = sh[SHP(k)];
            float2 Hm = sh[SHP(4096 - k)];
            float s, co;
            sincospif((float)k * (1.0f / 4096.0f), &s, &co);
            float aa = 0.5f * (1.0f - s);
            float bb = 0.5f * (1.0f + s);
            float ci = 0.5f * co;
            float2 P = make_float2(aa * Hk.x + bb * Hm.x, aa * Hk.y - bb * Hm.y);
            float2 Q = make_float2(-ci * (Hk.y + Hm.y), ci * (Hk.x - Hm.x));
            float2 S = make_float2(bb * Hk.x + aa * Hm.x, -bb * Hk.y + aa * Hm.y);
            outPQ[q] = make_float4(P.x, P.y, Q.x, Q.y);
            outS[q]  = S;
        }
    }
}

__global__ __launch_bounds__(TPB, 1)
void _ScaleFFTFilter_45380624449589_kernel(const float *__restrict__ x,
                                           float *__restrict__ y) {
    extern __shared__ float2 smem_raw[];
    float2 *sm = smem_raw;             // 4 columns * CST
    float2 *tw = smem_raw + 4 * CST;   // padded twiddle table

    const int tid = threadIdx.x;
    const int fg  = blockIdx.x >> 3;   // feature group (0..127)
    const int b   = blockIdx.x & 7;    // batch (0..7)
    const int f0  = fg * 4;
    const int col = tid >> 8;          // column owned in the middle phases
    const int u   = tid & 255;

    // twiddle table: tw[m] = e^{-2*pi*i*m/4096}, m < 256
    if (tid < TWN) {
        float s, co;
        sincospif((float)tid * (1.0f / 2048.0f), &s, &co);
        tw[PHYT(tid)] = make_float2(co, -s);
    }
    __syncthreads();

    // ---- fused: global load + pack + first fwd radix-16 pass (Q=256) ----
    {
        const int cc = tid & 3;
        const int j  = tid >> 2;       // 0..255
        const float *xc = x + ((size_t)b * 8192) * 512 + f0 + cc;
        float2 v[16];
        #pragma unroll
        for (int m = 0; m < 16; m++) {
            size_t row = (size_t)2 * (j + m * 256);
            v[m] = make_float2(__ldg(xc + row * 512), __ldg(xc + (row + 1) * 512));
        }
        dft16(v);
        store_twiddled<272>(sm + cc * CST, PHYS(j), v, tw[PHYT(j)]);
    }
    __syncthreads();

    // ---- middle fwd radix-16 pass, Q=16 (column-local) ----
    {
        float2 *Bp = sm + col * CST;
        int j = u & 15;
        int g = u >> 4;
        int p0 = PHYS(g * 256 + j);
        float2 v[16];
        #pragma unroll
        for (int m = 0; m < 16; m++) v[m] = Bp[p0 + m * 17];
        dft16(v);
        store_twiddled<17>(Bp, p0, v, tw[PHYT(j << 4)]);
    }
    BARCOL(col);

    {   // final forward radix-16 blocks (no twiddles, column-local)
        float2 *Bp = sm + col * CST;
        int p0 = PHYS(u * 16);
        float2 v[16];
        #pragma unroll
        for (int j = 0; j < 16; j++) v[j] = Bp[p0 + j];
        dft16(v);
        #pragma unroll
        for (int m = 0; m < 16; m++) Bp[p0 + m] = v[PERM16(m)];
    }
    BARCOL(col);

    // ---- filter (column-local): Zk' = P*Zk + Q*conj(Zm);
    //      Zm' = R*conj(Zk) + S*Zm with R = (-Q.x, Q.y) ----
    {
        float2 *Bp = sm + col * CST;
        const float4 *Hpq = g_HpackPQ + (size_t)(f0 + col) * 2048;
        const float2 *Hs  = g_HpackS  + (size_t)(f0 + col) * 2048;
        #pragma unroll
        for (int it = 0; it < 8; it++) {
            int q = it * 256 + u;
            float4 h1 = __ldg(Hpq + q);
            if (q == 0) {
                float2 z0 = Bp[0];
                float Y0 = (z0.x + z0.y) * h1.x;
                float YN = (z0.x - z0.y) * h1.y;
                Bp[0] = make_float2(0.5f * (Y0 + YN), 0.5f * (Y0 - YN));
                float2 z2 = Bp[8];   // PHYS(rev16(2048)) = 8
                Bp[8] = cmul(z2, make_float2(h1.z, h1.w));   // * conj(H2048)
            } else {
                float2 s2 = __ldg(Hs + q);
                int k = ((q & 7) << 8) | (((q >> 3) & 15) << 4) | (q >> 7);
                int pk = PHYS(rev16(k));
                int pm = PHYS(rev16(4096 - k));
                float2 Zk = Bp[pk];
                float2 Zm = Bp[pm];
                Bp[pk] = make_float2(
                    fmaf(h1.x, Zk.x, -h1.y * Zk.y) + fmaf(h1.z, Zm.x,  h1.w * Zm.y),
                    fmaf(h1.x, Zk.y,  h1.y * Zk.x) + fmaf(h1.w, Zm.x, -h1.z * Zm.y));
                Bp[pm] = make_float2(
                    fmaf(-h1.z, Zk.x, h1.w * Zk.y) + fmaf(s2.x, Zm.x, -s2.y * Zm.y),
                    fmaf( h1.w, Zk.x, h1.z * Zk.y) + fmaf(s2.x, Zm.y,  s2.y * Zm.x));
            }
        }
    }
    BARCOL(col);

    {   // first inverse radix-16 blocks (no twiddles, column-local)
        float2 *Bp = sm + col * CST;
        int p0 = PHYS(u * 16);
        float2 v[16];
        #pragma unroll
        for (int j = 0; j < 16; j++) {
            float2 w = Bp[p0 + j];
            v[j] = make_float2(w.x, -w.y);
        }
        dft16(v);
        #pragma unroll
        for (int m = 0; m < 16; m++) {
            float2 w = v[PERM16(m)];
            Bp[p0 + m] = make_float2(w.x, -w.y);
        }
    }
    BARCOL(col);

    // ---- middle inverse radix-16 pass, Q=16 (column-local) ----
    {
        float2 *Bp = sm + col * CST;
        int j = u & 15;
        int g = u >> 4;
        int p0 = PHYS(g * 256 + j);
        float2 v[16];
        load_twiddled_conj<17>(Bp, p0, v, tw[PHYT(j << 4)]);
        dft16(v);
        #pragma unroll
        for (int m = 0; m < 16; m++) {
            float2 t = v[PERM16(m)];
            Bp[p0 + m * 17] = make_float2(t.x, -t.y);
        }
    }
    __syncthreads();   // next phase reads across columns

    // ---- fused: last inverse pass (Q=256) + unpack + global store ----
    {
        const int cc = tid & 3;
        const int j  = tid >> 2;       // 0..255
        float2 *Bp = sm + cc * CST;
        float2 v[16];
        load_twiddled_conj<272>(Bp, PHYS(j), v, tw[PHYT(j)]);
        dft16(v);
        float *yc = y + ((size_t)b * 8192) * 512 + f0 + cc;
        const float SC = 1.0f / 4096.0f;
        #pragma unroll
        for (int m = 0; m < 16; m++) {
            float2 t = v[PERM16(m)];           // result = conj(t)
            size_t row = (size_t)2 * (j + m * 256);
            yc[row * 512]       = t.x * SC;
            yc[(row + 1) * 512] = -t.y * SC;
        }
    }
}

extern "C" void kernel_launch(void* const* d_in, const int* in_sizes, int n_in,
                              void* d_out, int out_size) {
    (void)in_sizes; (void)n_in; (void)out_size;
    const float  *x  = (const float*)d_in[0];
    const float2 *H2 = (const float2*)d_in[1];
    float        *y  = (float*)d_out;

    _permute_H_kernel<<<512, 512>>>(H2);

    const size_t smem_bytes = (size_t)(4 * CST + TWSZ) * sizeof(float2);  // ~141.7 KB
    cudaFuncSetAttribute(_ScaleFFTFilter_45380624449589_kernel,
                         cudaFuncAttributeMaxDynamicSharedMemorySize,
                         (int)smem_bytes);
    _ScaleFFTFilter_45380624449589_kernel<<<1024, TPB, smem_bytes>>>(x, y);
}

// round 12
// speedup vs baseline: 1.1424x; 1.0135x over previous
#include <cuda_runtime.h>
#include <cuda_bf16.h>
#include <cstddef>

#define TPB      1024
#define NFFT     4096
#define CST      4356                 // per-column smem stride (float2)
#define PHYS(i)  ((i) + ((i) >> 4))   // data padding: every 16 elements
#define PHYT(i)  ((i) + ((i) >> 4) + ((i) >> 6))  // twiddle-table padding
#define TWN      256
#define TWSZ     288                  // > PHYT(255) = 273
#define PERM16(m) ((((m) & 3) << 2) | ((m) >> 2))
// Prologue staging pad: lanes read k + {256a + 16b}; this pad spreads banks.
#define SHP(i)   ((i) + ((i) >> 4) + ((i) >> 7))

// Column-local barrier: 8 warps (256 threads) of one feature column.
#define BARCOL(c) asm volatile("bar.sync %0, 256;" :: "r"((c) + 1) : "memory")

// Scratch: filter as 2x2 complex linear map per (k, 4096-k) pair.
// Zk' = P*Zk + Q*conj(Zm); Zm' = R*conj(Zk) + S*Zm with R = -conj(Q).
// g_HpackPQ[f*2048+q] = (P.x,P.y,Q.x,Q.y); g_HpackS[f*2048+q] = (S.x,S.y).
// q==0 special: PQ slot 0 = (H0.re, HN.re, conjH2048.x, conjH2048.y).
__device__ float4 g_HpackPQ[512 * 2048];
__device__ float2 g_HpackS[512 * 2048];

__device__ __forceinline__ float2 cmul(float2 a, float2 b) {
    return make_float2(fmaf(a.x, b.x, -a.y * b.y), fmaf(a.x, b.y, a.y * b.x));
}
// a * conj(b)
__device__ __forceinline__ float2 cmulc(float2 a, float2 b) {
    return make_float2(fmaf(a.x, b.x, a.y * b.y), fmaf(a.y, b.x, -a.x * b.y));
}

__device__ __forceinline__ void dft4(float2 &a, float2 &b, float2 &c, float2 &d) {
    float2 t0 = make_float2(a.x + c.x, a.y + c.y);
    float2 t1 = make_float2(a.x - c.x, a.y - c.y);
    float2 t2 = make_float2(b.x + d.x, b.y + d.y);
    float2 t3 = make_float2(b.x - d.x, b.y - d.y);
    a = make_float2(t0.x + t2.x, t0.y + t2.y);
    c = make_float2(t0.x - t2.x, t0.y - t2.y);
    b = make_float2(t1.x + t3.y, t1.y - t3.x);   // t1 - i*t3
    d = make_float2(t1.x - t3.y, t1.y + t3.x);   // t1 + i*t3
}

// 16-point forward DFT, natural input order. Output X[m] ends at slot PERM16(m).
__device__ __forceinline__ void dft16(float2 v[16]) {
    #pragma unroll
    for (int j0 = 0; j0 < 4; j0++) dft4(v[j0], v[j0 + 4], v[j0 + 8], v[j0 + 12]);
    const float C1 = 0.92387953251128675613f;   // cos(pi/8)
    const float S1 = 0.38268343236508977173f;   // sin(pi/8)
    const float C2 = 0.70710678118654752440f;   // sqrt(2)/2
    v[5]  = cmul(v[5],  make_float2( C1, -S1));
    v[9]  = cmul(v[9],  make_float2( C2, -C2));
    v[13] = cmul(v[13], make_float2( S1, -C1));
    v[6]  = cmul(v[6],  make_float2( C2, -C2));
    { float2 t = v[10]; v[10] = make_float2(t.y, -t.x); }
    v[14] = cmul(v[14], make_float2(-C2, -C2));
    v[7]  = cmul(v[7],  make_float2( S1, -C1));
    v[11] = cmul(v[11], make_float2(-C2, -C2));
    v[15] = cmul(v[15], make_float2(-C1,  S1));
    #pragma unroll
    for (int m0 = 0; m0 < 4; m0++) dft4(v[4*m0], v[4*m0+1], v[4*m0+2], v[4*m0+3]);
}

// Digit reversal for radices [16,16,16] DIF order (12-bit index).
__device__ __forceinline__ int rev16(int k) {
    return ((k & 15) << 8) | (k & 0xF0) | (k >> 8);
}

// Twiddled store phase: dual even/odd chains (depth 7 each, not 14).
template <int QP>
__device__ __forceinline__ void store_twiddled(float2 *Bp, int p0, float2 v[16], float2 w1) {
    float2 w2 = cmul(w1, w1);
    Bp[p0] = v[0];
    Bp[p0 + QP] = cmul(v[PERM16(1)], w1);
    Bp[p0 + 2 * QP] = cmul(v[PERM16(2)], w2);
    float2 wo = w1;
    float2 we = w2;
    #pragma unroll
    for (int m = 3; m < 16; m += 2) {
        wo = cmul(wo, w2);
        Bp[p0 + m * QP] = cmul(v[PERM16(m)], wo);
    }
    #pragma unroll
    for (int m = 4; m < 16; m += 2) {
        we = cmul(we, w2);
        Bp[p0 + m * QP] = cmul(v[PERM16(m)], we);
    }
}

// Twiddled (conjugate) load phase for inverse passes, dual chains.
// v[m] = conj(raw * conj(w^m)) = cmulc(w^m, raw).
template <int QP>
__device__ __forceinline__ void load_twiddled_conj(const float2 *Bp, int p0, float2 v[16], float2 w1) {
    float2 w2 = cmul(w1, w1);
    {
        float2 u = Bp[p0];
        v[0] = make_float2(u.x, -u.y);
    }
    v[1] = cmulc(w1, Bp[p0 + QP]);
    v[2] = cmulc(w2, Bp[p0 + 2 * QP]);
    float2 wo = w1;
    float2 we = w2;
    #pragma unroll
    for (int m = 3; m < 16; m += 2) {
        wo = cmul(wo, w2);
        v[m] = cmulc(wo, Bp[p0 + m * QP]);
    }
    #pragma unroll
    for (int m = 4; m < 16; m += 2) {
        we = cmul(we, w2);
        v[m] = cmulc(we, Bp[p0 + m * QP]);
    }
}

// Prologue: build coefficient pack. Trig via two-level table
// (144 sincospif per CTA instead of 2048) — prologue was issue-bound on
// the ~30-instruction sincospif routine.
__global__ __launch_bounds__(512) void _permute_H_kernel(const float2 *__restrict__ H2) {
    __shared__ float2 sh[SHP(4096) + 8];
    __shared__ float2 tlo[16];    // e^{-i pi l /4096},    l = 0..15
    __shared__ float2 thi[128];   // e^{-i pi 16h /4096},  h = 0..127
    const int f = blockIdx.x;
    const float2 *Hb = H2 + (size_t)f * 4097;
    if (threadIdx.x < 144) {
        float s, co;
        if (threadIdx.x < 16) {
            sincospif((float)threadIdx.x * (1.0f / 4096.0f), &s, &co);
            tlo[threadIdx.x] = make_float2(co, -s);
        } else {
            sincospif((float)(threadIdx.x - 16) * (16.0f / 4096.0f), &s, &co);
            thi[threadIdx.x - 16] = make_float2(co, -s);
        }
    }
    for (int i = threadIdx.x; i < 4097; i += 512) sh[SHP(i)] = __ldg(Hb + i);
    __syncthreads();
    float4 *outPQ = g_HpackPQ + (size_t)f * 2048;
    float2 *outS  = g_HpackS  + (size_t)f * 2048;
    #pragma unroll
    for (int it = 0; it < 4; it++) {
        int q = it * 512 + threadIdx.x;
        if (q == 0) {
            float2 hM = sh[SHP(2048)];
            outPQ[0] = make_float4(sh[SHP(0)].x, sh[SHP(4096)].x, hM.x, -hM.y);
            outS[0]  = make_float2(0.f, 0.f);
        } else {
            int k = ((q & 7) << 8) | (((q >> 3) & 15) << 4) | (q >> 7);
            float2 Hk = sh[SHP(k)];
            float2 Hm = sh[SHP(4096 - k)];
            float2 W = cmul(thi[k >> 4], tlo[k & 15]);   // e^{-i pi k/4096}
            float co = W.x;
            float s  = -W.y;
            float aa = 0.5f * (1.0f - s);
            float bb = 0.5f * (1.0f + s);
            float ci = 0.5f * co;
            float2 P = make_float2(aa * Hk.x + bb * Hm.x, aa * Hk.y - bb * Hm.y);
            float2 Q = make_float2(-ci * (Hk.y + Hm.y), ci * (Hk.x - Hm.x));
            float2 S = make_float2(bb * Hk.x + aa * Hm.x, -bb * Hk.y + aa * Hm.y);
            outPQ[q] = make_float4(P.x, P.y, Q.x, Q.y);
            outS[q]  = S;
        }
    }
}

__global__ __launch_bounds__(TPB, 1)
void _ScaleFFTFilter_45380624449589_kernel(const float *__restrict__ x,
                                           float *__restrict__ y) {
    extern __shared__ float2 smem_raw[];
    float2 *sm = smem_raw;             // 4 columns * CST
    float2 *tw = smem_raw + 4 * CST;   // padded twiddle table

    const int tid = threadIdx.x;
    const int fg  = blockIdx.x >> 3;   // feature group (0..127)
    const int b   = blockIdx.x & 7;    // batch (0..7)
    const int f0  = fg * 4;
    const int col = tid >> 8;          // column owned in the middle phases
    const int u   = tid & 255;

    // twiddle table: tw[m] = e^{-2*pi*i*m/4096}, m < 256
    if (tid < TWN) {
        float s, co;
        sincospif((float)tid * (1.0f / 2048.0f), &s, &co);
        tw[PHYT(tid)] = make_float2(co, -s);
    }
    __syncthreads();

    // ---- fused: global load + pack + first fwd radix-16 pass (Q=256) ----
    {
        const int cc = tid & 3;
        const int j  = tid >> 2;       // 0..255
        const float *xc = x + ((size_t)b * 8192) * 512 + f0 + cc;
        float2 v[16];
        #pragma unroll
        for (int m = 0; m < 16; m++) {
            size_t row = (size_t)2 * (j + m * 256);
            v[m] = make_float2(__ldg(xc + row * 512), __ldg(xc + (row + 1) * 512));
        }
        dft16(v);
        store_twiddled<272>(sm + cc * CST, PHYS(j), v, tw[PHYT(j)]);
    }
    __syncthreads();

    // ---- middle fwd radix-16 pass, Q=16 (column-local) ----
    {
        float2 *Bp = sm + col * CST;
        int j = u & 15;
        int g = u >> 4;
        int p0 = PHYS(g * 256 + j);
        float2 v[16];
        #pragma unroll
        for (int m = 0; m < 16; m++) v[m] = Bp[p0 + m * 17];
        dft16(v);
        store_twiddled<17>(Bp, p0, v, tw[PHYT(j << 4)]);
    }
    BARCOL(col);

    {   // final forward radix-16 blocks (no twiddles, column-local)
        float2 *Bp = sm + col * CST;
        int p0 = PHYS(u * 16);
        float2 v[16];
        #pragma unroll
        for (int j = 0; j < 16; j++) v[j] = Bp[p0 + j];
        dft16(v);
        #pragma unroll
        for (int m = 0; m < 16; m++) Bp[p0 + m] = v[PERM16(m)];
    }
    BARCOL(col);

    // ---- filter (column-local): Zk' = P*Zk + Q*conj(Zm);
    //      Zm' = R*conj(Zk) + S*Zm with R = (-Q.x, Q.y) ----
    {
        float2 *Bp = sm + col * CST;
        const float4 *Hpq = g_HpackPQ + (size_t)(f0 + col) * 2048;
        const float2 *Hs  = g_HpackS  + (size_t)(f0 + col) * 2048;
        #pragma unroll
        for (int it = 0; it < 8; it++) {
            int q = it * 256 + u;
            float4 h1 = __ldg(Hpq + q);
            if (q == 0) {
                float2 z0 = Bp[0];
                float Y0 = (z0.x + z0.y) * h1.x;
                float YN = (z0.x - z0.y) * h1.y;
                Bp[0] = make_float2(0.5f * (Y0 + YN), 0.5f * (Y0 - YN));
                float2 z2 = Bp[8];   // PHYS(rev16(2048)) = 8
                Bp[8] = cmul(z2, make_float2(h1.z, h1.w));   // * conj(H2048)
            } else {
                float2 s2 = __ldg(Hs + q);
                int k = ((q & 7) << 8) | (((q >> 3) & 15) << 4) | (q >> 7);
                int pk = PHYS(rev16(k));
                int pm = PHYS(rev16(4096 - k));
                float2 Zk = Bp[pk];
                float2 Zm = Bp[pm];
                Bp[pk] = make_float2(
                    fmaf(h1.x, Zk.x, -h1.y * Zk.y) + fmaf(h1.z, Zm.x,  h1.w * Zm.y),
                    fmaf(h1.x, Zk.y,  h1.y * Zk.x) + fmaf(h1.w, Zm.x, -h1.z * Zm.y));
                Bp[pm] = make_float2(
                    fmaf(-h1.z, Zk.x, h1.w * Zk.y) + fmaf(s2.x, Zm.x, -s2.y * Zm.y),
                    fmaf( h1.w, Zk.x, h1.z * Zk.y) + fmaf(s2.x, Zm.y,  s2.y * Zm.x));
            }
        }
    }
    BARCOL(col);

    {   // first inverse radix-16 blocks (no twiddles, column-local)
        float2 *Bp = sm + col * CST;
        int p0 = PHYS(u * 16);
        float2 v[16];
        #pragma unroll
        for (int j = 0; j < 16; j++) {
            float2 w = Bp[p0 + j];
            v[j] = make_float2(w.x, -w.y);
        }
        dft16(v);
        #pragma unroll
        for (int m = 0; m < 16; m++) {
            float2 w = v[PERM16(m)];
            Bp[p0 + m] = make_float2(w.x, -w.y);
        }
    }
    BARCOL(col);

    // ---- middle inverse radix-16 pass, Q=16 (column-local) ----
    {
        float2 *Bp = sm + col * CST;
        int j = u & 15;
        int g = u >> 4;
        int p0 = PHYS(g * 256 + j);
        float2 v[16];
        load_twiddled_conj<17>(Bp, p0, v, tw[PHYT(j << 4)]);
        dft16(v);
        #pragma unroll
        for (int m = 0; m < 16; m++) {
            float2 t = v[PERM16(m)];
            Bp[p0 + m * 17] = make_float2(t.x, -t.y);
        }
    }
    __syncthreads();   // next phase reads across columns

    // ---- fused: last inverse pass (Q=256) + unpack + global store ----
    {
        const int cc = tid & 3;
        const int j  = tid >> 2;       // 0..255
        float2 *Bp = sm + cc * CST;
        float2 v[16];
        load_twiddled_conj<272>(Bp, PHYS(j), v, tw[PHYT(j)]);
        dft16(v);
        float *yc = y + ((size_t)b * 8192) * 512 + f0 + cc;
        const float SC = 1.0f / 4096.0f;
        #pragma unroll
        for (int m = 0; m < 16; m++) {
            float2 t = v[PERM16(m)];           // result = conj(t)
            size_t row = (size_t)2 * (j + m * 256);
            yc[row * 512]       = t.x * SC;
            yc[(row + 1) * 512] = -t.y * SC;
        }
    }
}

extern "C" void kernel_launch(void* const* d_in, const int* in_sizes, int n_in,
                              void* d_out, int out_size) {
    (void)in_sizes; (void)n_in; (void)out_size;
    const float  *x  = (const float*)d_in[0];
    const float2 *H2 = (const float2*)d_in[1];
    float        *y  = (float*)d_out;

    _permute_H_kernel<<<512, 512>>>(H2);

    const size_t smem_bytes = (size_t)(4 * CST + TWSZ) * sizeof(float2);  // ~141.7 KB
    cudaFuncSetAttribute(_ScaleFFTFilter_45380624449589_kernel,
                         cudaFuncAttributeMaxDynamicSharedMemorySize,
                         (int)smem_bytes);
    _ScaleFFTFilter_45380624449589_kernel<<<1024, TPB, smem_bytes>>>(x, y);
}